// round 7
// baseline (speedup 1.0000x reference)
#include <cuda_runtime.h>
#include <cuda_bf16.h>
#include <cstdint>

// Problem constants (fixed by the dataset)
#define MAXN 50000
#define MAXE 800000
#define FD   128     // node/edge feature dim
#define HD   128     // h dim
#define OD   256     // edge output dim

// ---------------- device scratch (no allocations allowed) ----------------
__device__ float g_sum[(size_t)MAXN * FD];     // segment sums of efeats by v
__device__ int   g_cnt[MAXN];                  // in-degree
__device__ float g_cat[(size_t)MAXN * 256];    // [nfeats | h_neigh]
__device__ float g_P[(size_t)MAXN * 512];      // [P_u (256) | P_v (256)] per node

// ---------------- kernel 1: zero scratch ----------------
__global__ void zero_kernel(int N) {
    size_t total = (size_t)N * FD;
    for (size_t i = (size_t)blockIdx.x * blockDim.x + threadIdx.x; i < total;
         i += (size_t)gridDim.x * blockDim.x)
        g_sum[i] = 0.0f;
    for (int i = blockIdx.x * blockDim.x + threadIdx.x; i < N;
         i += gridDim.x * blockDim.x)
        g_cnt[i] = 0;
}

// ---------------- kernel 2: scatter mean (sums + counts) ----------------
// one warp per edge; each lane adds a float4 worth (4 scalar atomics -> RED)
__global__ void scatter_kernel(const float* __restrict__ efeats,
                               const int* __restrict__ v, int E) {
    int w = (blockIdx.x * blockDim.x + threadIdx.x) >> 5;
    int lane = threadIdx.x & 31;
    if (w >= E) return;
    int dst = v[w];
    float4 val = ((const float4*)(efeats + (size_t)w * FD))[lane];
    float* s = g_sum + (size_t)dst * FD + lane * 4;
    atomicAdd(s + 0, val.x);
    atomicAdd(s + 1, val.y);
    atomicAdd(s + 2, val.z);
    atomicAdd(s + 3, val.w);
    if (lane == 0) atomicAdd(&g_cnt[dst], 1);
}

// ---------------- kernel 3: build cat = [nfeats | sums/max(cnt,1)] ------
__global__ void cat_kernel(const float* __restrict__ nfeats, int N) {
    int total4 = N * 64;  // 256 floats per node = 64 float4
    int t = blockIdx.x * blockDim.x + threadIdx.x;
    if (t >= total4) return;
    int n = t >> 6;
    int q = t & 63;
    float4* out4 = (float4*)g_cat;
    if (q < 32) {
        out4[(size_t)n * 64 + q] = ((const float4*)nfeats)[(size_t)n * 32 + q];
    } else {
        float inv = 1.0f / fmaxf((float)g_cnt[n], 1.0f);
        float4 s = ((const float4*)g_sum)[(size_t)n * 32 + (q - 32)];
        s.x *= inv; s.y *= inv; s.z *= inv; s.w *= inv;
        out4[(size_t)n * 64 + q] = s;
    }
}

// ---------------- SGEMM: C[m][n] = act( sum_k A[m][k]*B[n][k] + bias[n] )
// 128x128 tile, BK=16, 256 threads, 8x8 microtile.
template <bool RELU, bool HAS_BIAS>
__global__ void sgemm_kernel(const float* __restrict__ A, int lda,
                             const float* __restrict__ B, int ldb,
                             const float* __restrict__ bias,
                             float* __restrict__ C, int ldc,
                             int M, int N, int K) {
    __shared__ float As[16][132];
    __shared__ float Bs[16][132];

    int tid = threadIdx.x;
    int bm = blockIdx.y * 128;
    int bn = blockIdx.x * 128;

    int tx = tid & 15;       // n-direction (16 threads)
    int ty = tid >> 4;       // m-direction (16 threads)
    int tm = ty * 8;
    int tn = tx * 8;

    float acc[8][8];
#pragma unroll
    for (int i = 0; i < 8; i++)
#pragma unroll
        for (int j = 0; j < 8; j++) acc[i][j] = 0.0f;

    for (int k0 = 0; k0 < K; k0 += 16) {
        // load A tile [128 rows m][16 k] -> As[k][m]
#pragma unroll
        for (int i = 0; i < 2; i++) {
            int slot = tid + i * 256;        // 512 float4 slots
            int row = slot >> 2;
            int kq = slot & 3;
            int gm = bm + row;
            float4 val = make_float4(0.f, 0.f, 0.f, 0.f);
            if (gm < M)
                val = *(const float4*)(A + (size_t)gm * lda + k0 + kq * 4);
            As[kq * 4 + 0][row] = val.x;
            As[kq * 4 + 1][row] = val.y;
            As[kq * 4 + 2][row] = val.z;
            As[kq * 4 + 3][row] = val.w;
        }
        // load B tile [128 rows n][16 k] -> Bs[k][n]
#pragma unroll
        for (int i = 0; i < 2; i++) {
            int slot = tid + i * 256;
            int row = slot >> 2;
            int kq = slot & 3;
            int gn = bn + row;
            float4 val = make_float4(0.f, 0.f, 0.f, 0.f);
            if (gn < N)
                val = *(const float4*)(B + (size_t)gn * ldb + k0 + kq * 4);
            Bs[kq * 4 + 0][row] = val.x;
            Bs[kq * 4 + 1][row] = val.y;
            Bs[kq * 4 + 2][row] = val.z;
            Bs[kq * 4 + 3][row] = val.w;
        }
        __syncthreads();

#pragma unroll
        for (int kk = 0; kk < 16; kk++) {
            float4 a0 = *(const float4*)&As[kk][tm];
            float4 a1 = *(const float4*)&As[kk][tm + 4];
            float4 b0 = *(const float4*)&Bs[kk][tn];
            float4 b1 = *(const float4*)&Bs[kk][tn + 4];
            float a[8] = {a0.x, a0.y, a0.z, a0.w, a1.x, a1.y, a1.z, a1.w};
            float b[8] = {b0.x, b0.y, b0.z, b0.w, b1.x, b1.y, b1.z, b1.w};
#pragma unroll
            for (int i = 0; i < 8; i++)
#pragma unroll
                for (int j = 0; j < 8; j++) acc[i][j] += a[i] * b[j];
        }
        __syncthreads();
    }

    // epilogue
    float bfr[8];
#pragma unroll
    for (int j = 0; j < 8; j++)
        bfr[j] = HAS_BIAS ? bias[bn + tn + j] : 0.0f;

#pragma unroll
    for (int i = 0; i < 8; i++) {
        int gm = bm + tm + i;
        if (gm >= M) continue;
        float r[8];
#pragma unroll
        for (int j = 0; j < 8; j++) {
            float x = acc[i][j] + bfr[j];
            if (RELU) x = fmaxf(x, 0.0f);
            r[j] = x;
        }
        float* cp = C + (size_t)gm * ldc + bn + tn;
        *(float4*)(cp + 0) = make_float4(r[0], r[1], r[2], r[3]);
        *(float4*)(cp + 4) = make_float4(r[4], r[5], r[6], r[7]);
    }
}

// ---------------- kernel 6: edge output = P_u[u] + P_v[v] + b -----------
// one warp per edge; each lane handles 2 float4 (8 floats) of the 256 outputs
__global__ void edge_kernel(const int* __restrict__ u,
                            const int* __restrict__ v,
                            const float* __restrict__ W_edge_b,
                            float* __restrict__ out, int E) {
    int w = (blockIdx.x * blockDim.x + threadIdx.x) >> 5;
    int lane = threadIdx.x & 31;
    if (w >= E) return;
    int uu = u[w];
    int vv = v[w];
    const float4* pu = (const float4*)(g_P + (size_t)uu * 512);        // cols 0..255
    const float4* pv = (const float4*)(g_P + (size_t)vv * 512 + 256);  // cols 256..511
    const float4* b4 = (const float4*)W_edge_b;
    float4* o4 = (float4*)(out + (size_t)w * OD);
#pragma unroll
    for (int i = 0; i < 2; i++) {
        int idx = lane + i * 32;  // 0..63
        float4 a = pu[idx];
        float4 c = pv[idx];
        float4 bb = __ldg(&b4[idx]);
        o4[idx] = make_float4(a.x + c.x + bb.x, a.y + c.y + bb.y,
                              a.z + c.z + bb.z, a.w + c.w + bb.w);
    }
}

// ---------------- launcher ----------------
extern "C" void kernel_launch(void* const* d_in, const int* in_sizes, int n_in,
                              void* d_out, int out_size) {
    const float* nfeats    = (const float*)d_in[0];  // [N,1,128]
    const float* efeats    = (const float*)d_in[1];  // [E,1,128]
    const int*   u         = (const int*)d_in[2];    // [E]
    const int*   v         = (const int*)d_in[3];    // [E]
    const float* W_apply_w = (const float*)d_in[4];  // [128,256]
    const float* W_apply_b = (const float*)d_in[5];  // [128]
    const float* W_edge_w  = (const float*)d_in[6];  // [256,256]
    const float* W_edge_b  = (const float*)d_in[7];  // [256]
    (void)n_in; (void)out_size;

    const int N = in_sizes[0] / FD;   // 50000
    const int E = in_sizes[2];        // 800000

    float* h_out    = (float*)d_out;                       // [N,128]
    float* edge_out = (float*)d_out + (size_t)N * HD;      // [E,256]

    // Resolve device-symbol addresses for use as kernel arguments.
    // (Passing a __device__ array from host code directly is invalid — that
    //  was the Round-4 bug. cudaGetSymbolAddress is a host API, not a stream
    //  op: graph-capture safe, no allocation.)
    float* p_cat = nullptr;
    float* p_P   = nullptr;
    cudaGetSymbolAddress((void**)&p_cat, g_cat);
    cudaGetSymbolAddress((void**)&p_P,   g_P);

    // 1. zero scratch
    zero_kernel<<<1024, 1024>>>(N);

    // 2. segment sums + counts (atomics)
    {
        int warps_per_block = 8;
        int blocks = (E + warps_per_block - 1) / warps_per_block;
        scatter_kernel<<<blocks, warps_per_block * 32>>>(efeats, v, E);
    }

    // 3. build cat = [nfeats | mean]
    {
        int total4 = N * 64;
        cat_kernel<<<(total4 + 255) / 256, 256>>>(nfeats, N);
    }

    // 4. h = relu(cat @ W_apply^T + b)    M=N, N=128, K=256
    {
        dim3 grid(1, (N + 127) / 128);
        sgemm_kernel<true, true><<<grid, 256>>>(
            p_cat, 256, W_apply_w, 256, W_apply_b, h_out, HD, N, HD, 256);
    }

    // 5a. P_u = h @ W_u^T   (W_u = W_edge_w[:, :128]) -> g_P cols [0,256)
    {
        dim3 grid(2, (N + 127) / 128);
        sgemm_kernel<false, false><<<grid, 256>>>(
            h_out, HD, W_edge_w, 256, nullptr, p_P, 512, N, 256, HD);
    }
    // 5b. P_v = h @ W_v^T   (W_v = W_edge_w[:, 128:]) -> g_P cols [256,512)
    {
        dim3 grid(2, (N + 127) / 128);
        sgemm_kernel<false, false><<<grid, 256>>>(
            h_out, HD, W_edge_w + 128, 256, nullptr, p_P + 256, 512, N, 256, HD);
    }

    // 6. edge = P_u[u] + P_v[v] + b
    {
        int warps_per_block = 8;
        int blocks = (E + warps_per_block - 1) / warps_per_block;
        edge_kernel<<<blocks, warps_per_block * 32>>>(u, v, W_edge_b, edge_out, E);
    }
}

// round 8
// speedup vs baseline: 1.2791x; 1.2791x over previous
#include <cuda_runtime.h>
#include <cuda_bf16.h>
#include <cstdint>

// Problem constants (fixed by the dataset)
#define MAXN 50000
#define MAXE 800000
#define FD   128     // node/edge feature dim
#define HD   128     // h dim
#define OD   256     // edge output dim

// ---------------- device scratch (no allocations allowed) ----------------
__device__ float g_sum[(size_t)MAXN * FD];      // segment sums of efeats by v
__device__ int   g_cnt[MAXN];                   // in-degree
__device__ float g_cat[(size_t)MAXN * 256];     // [nfeats | h_neigh]
__device__ float g_P[(size_t)MAXN * 512];       // [P_u (256) | P_v (256)] per node
__device__ float g_Wcat[512 * 128];             // packed [W_u ; W_v], rows=512 outs, k=128

// ---------------- kernel 1: zero scratch ----------------
__global__ void zero_kernel(int N) {
    size_t total4 = (size_t)N * (FD / 4);
    float4 z = make_float4(0.f, 0.f, 0.f, 0.f);
    float4* s4 = (float4*)g_sum;
    for (size_t i = (size_t)blockIdx.x * blockDim.x + threadIdx.x; i < total4;
         i += (size_t)gridDim.x * blockDim.x)
        s4[i] = z;
    for (int i = blockIdx.x * blockDim.x + threadIdx.x; i < N;
         i += gridDim.x * blockDim.x)
        g_cnt[i] = 0;
}

// ---------------- kernel 2: scatter mean via vector RED ----------------
// one warp per edge; each lane issues ONE red.global.add.v4.f32
__global__ void scatter_kernel(const float* __restrict__ efeats,
                               const int* __restrict__ v, int E) {
    int w = (blockIdx.x * blockDim.x + threadIdx.x) >> 5;
    int lane = threadIdx.x & 31;
    if (w >= E) return;
    int dst = __ldg(&v[w]);
    float4 val = __ldg(((const float4*)(efeats + (size_t)w * FD)) + lane);
    float* s = g_sum + (size_t)dst * FD + lane * 4;
    asm volatile("red.global.add.v4.f32 [%0], {%1, %2, %3, %4};"
                 :: "l"(s), "f"(val.x), "f"(val.y), "f"(val.z), "f"(val.w)
                 : "memory");
    if (lane == 0) atomicAdd(&g_cnt[dst], 1);
}

// ---------------- kernel 3: build cat = [nfeats | sums/max(cnt,1)] ------
__global__ void cat_kernel(const float* __restrict__ nfeats, int N) {
    int total4 = N * 64;  // 256 floats per node = 64 float4
    int t = blockIdx.x * blockDim.x + threadIdx.x;
    if (t >= total4) return;
    int n = t >> 6;
    int q = t & 63;
    float4* out4 = (float4*)g_cat;
    if (q < 32) {
        out4[(size_t)n * 64 + q] = ((const float4*)nfeats)[(size_t)n * 32 + q];
    } else {
        float inv = 1.0f / fmaxf((float)g_cnt[n], 1.0f);
        float4 s = ((const float4*)g_sum)[(size_t)n * 32 + (q - 32)];
        s.x *= inv; s.y *= inv; s.z *= inv; s.w *= inv;
        out4[(size_t)n * 64 + q] = s;
    }
}

// ---------------- kernel 3b: pack Wcat = [W_u ; W_v] ----------------
// Wcat[n][k] = n<256 ? W_edge_w[n][k] : W_edge_w[n-256][128+k]   (n<512, k<128)
__global__ void wpack_kernel(const float* __restrict__ W_edge_w) {
    int t = blockIdx.x * blockDim.x + threadIdx.x;  // 512*32 float4 = 16384
    if (t >= 512 * 32) return;
    int n = t >> 5;
    int kq = t & 31;
    const float* src = (n < 256) ? (W_edge_w + (size_t)n * 256 + kq * 4)
                                 : (W_edge_w + (size_t)(n - 256) * 256 + 128 + kq * 4);
    ((float4*)g_Wcat)[t] = *(const float4*)src;
}

// ---------------- fused GEMM: h = relu(cat@Wa^T + b); P = h@Wcat^T ------
// One 128-row M-tile per block. Stage 1: K=256 -> h tile kept in smem
// (transposed [k][m]) and written to gmem. Stage 2: 4 chunks of 128 output
// cols, K=128, A read from smem.
__global__ __launch_bounds__(256, 2) void gemm45_kernel(
    const float* __restrict__ Wa,    // [128][256]
    const float* __restrict__ Wab,   // [128]
    float* __restrict__ h_out,       // [M][128]
    int M)
{
    extern __shared__ float smem[];
    float* h_s = smem;                 // [128][132]  indexed [k][m]
    float* As  = smem + 128 * 132;     // [16][132]
    float* Bs  = As + 16 * 132;        // [16][132]

    int tid = threadIdx.x;
    int bm = blockIdx.x * 128;
    int tx = tid & 15;
    int ty = tid >> 4;
    int tm = ty * 8;
    int tn = tx * 8;

    float acc[8][8];
#pragma unroll
    for (int i = 0; i < 8; i++)
#pragma unroll
        for (int j = 0; j < 8; j++) acc[i][j] = 0.0f;

    // ---------------- stage 1: h = relu(cat @ Wa^T + b), K=256 ----------
    for (int k0 = 0; k0 < 256; k0 += 16) {
#pragma unroll
        for (int i = 0; i < 2; i++) {
            int slot = tid + i * 256;   // 512 float4 slots
            int row = slot >> 2;
            int kq = slot & 3;
            int gm = bm + row;
            float4 a = make_float4(0.f, 0.f, 0.f, 0.f);
            if (gm < M)
                a = *(const float4*)(g_cat + (size_t)gm * 256 + k0 + kq * 4);
            As[(kq * 4 + 0) * 132 + row] = a.x;
            As[(kq * 4 + 1) * 132 + row] = a.y;
            As[(kq * 4 + 2) * 132 + row] = a.z;
            As[(kq * 4 + 3) * 132 + row] = a.w;
            float4 b = *(const float4*)(Wa + (size_t)row * 256 + k0 + kq * 4);
            Bs[(kq * 4 + 0) * 132 + row] = b.x;
            Bs[(kq * 4 + 1) * 132 + row] = b.y;
            Bs[(kq * 4 + 2) * 132 + row] = b.z;
            Bs[(kq * 4 + 3) * 132 + row] = b.w;
        }
        __syncthreads();
#pragma unroll
        for (int kk = 0; kk < 16; kk++) {
            float4 a0 = *(const float4*)&As[kk * 132 + tm];
            float4 a1 = *(const float4*)&As[kk * 132 + tm + 4];
            float4 b0 = *(const float4*)&Bs[kk * 132 + tn];
            float4 b1 = *(const float4*)&Bs[kk * 132 + tn + 4];
            float a[8] = {a0.x, a0.y, a0.z, a0.w, a1.x, a1.y, a1.z, a1.w};
            float b[8] = {b0.x, b0.y, b0.z, b0.w, b1.x, b1.y, b1.z, b1.w};
#pragma unroll
            for (int i = 0; i < 8; i++)
#pragma unroll
                for (int j = 0; j < 8; j++) acc[i][j] += a[i] * b[j];
        }
        __syncthreads();
    }

    // epilogue 1: bias + relu (in place), write h to gmem + smem (transposed)
#pragma unroll
    for (int j = 0; j < 8; j++) {
        float bj = __ldg(&Wab[tn + j]);
#pragma unroll
        for (int i = 0; i < 8; i++)
            acc[i][j] = fmaxf(acc[i][j] + bj, 0.0f);
    }
#pragma unroll
    for (int i = 0; i < 8; i++) {
        int gm = bm + tm + i;
        if (gm < M) {
            float* cp = h_out + (size_t)gm * HD + tn;
            *(float4*)(cp + 0) = make_float4(acc[i][0], acc[i][1], acc[i][2], acc[i][3]);
            *(float4*)(cp + 4) = make_float4(acc[i][4], acc[i][5], acc[i][6], acc[i][7]);
        }
    }
#pragma unroll
    for (int j = 0; j < 8; j++) {
        *(float4*)&h_s[(tn + j) * 132 + tm] =
            make_float4(acc[0][j], acc[1][j], acc[2][j], acc[3][j]);
        *(float4*)&h_s[(tn + j) * 132 + tm + 4] =
            make_float4(acc[4][j], acc[5][j], acc[6][j], acc[7][j]);
    }
    __syncthreads();

    // ---------------- stage 2: P = h @ Wcat^T, K=128, 4 output chunks ---
    for (int chunk = 0; chunk < 4; chunk++) {
#pragma unroll
        for (int i = 0; i < 8; i++)
#pragma unroll
            for (int j = 0; j < 8; j++) acc[i][j] = 0.0f;

        for (int k0 = 0; k0 < 128; k0 += 16) {
#pragma unroll
            for (int i = 0; i < 2; i++) {
                int slot = tid + i * 256;
                int row = slot >> 2;
                int kq = slot & 3;
                float4 b = *(const float4*)(g_Wcat + (size_t)(chunk * 128 + row) * 128
                                            + k0 + kq * 4);
                Bs[(kq * 4 + 0) * 132 + row] = b.x;
                Bs[(kq * 4 + 1) * 132 + row] = b.y;
                Bs[(kq * 4 + 2) * 132 + row] = b.z;
                Bs[(kq * 4 + 3) * 132 + row] = b.w;
            }
            __syncthreads();
#pragma unroll
            for (int kk = 0; kk < 16; kk++) {
                float4 a0 = *(const float4*)&h_s[(k0 + kk) * 132 + tm];
                float4 a1 = *(const float4*)&h_s[(k0 + kk) * 132 + tm + 4];
                float4 b0 = *(const float4*)&Bs[kk * 132 + tn];
                float4 b1 = *(const float4*)&Bs[kk * 132 + tn + 4];
                float a[8] = {a0.x, a0.y, a0.z, a0.w, a1.x, a1.y, a1.z, a1.w};
                float b[8] = {b0.x, b0.y, b0.z, b0.w, b1.x, b1.y, b1.z, b1.w};
#pragma unroll
                for (int i = 0; i < 8; i++)
#pragma unroll
                    for (int j = 0; j < 8; j++) acc[i][j] += a[i] * b[j];
            }
            __syncthreads();
        }

#pragma unroll
        for (int i = 0; i < 8; i++) {
            int gm = bm + tm + i;
            if (gm < M) {
                float* cp = g_P + (size_t)gm * 512 + chunk * 128 + tn;
                *(float4*)(cp + 0) = make_float4(acc[i][0], acc[i][1], acc[i][2], acc[i][3]);
                *(float4*)(cp + 4) = make_float4(acc[i][4], acc[i][5], acc[i][6], acc[i][7]);
            }
        }
    }
}

// ---------------- kernel 6: edge output = P_u[u] + P_v[v] + b -----------
// one warp per edge; streaming stores keep g_P resident in L2
__global__ void edge_kernel(const int* __restrict__ u,
                            const int* __restrict__ v,
                            const float* __restrict__ W_edge_b,
                            float* __restrict__ out, int E) {
    int w = (blockIdx.x * blockDim.x + threadIdx.x) >> 5;
    int lane = threadIdx.x & 31;
    if (w >= E) return;
    int uu = __ldg(&u[w]);
    int vv = __ldg(&v[w]);
    const float4* pu = (const float4*)(g_P + (size_t)uu * 512);        // cols 0..255
    const float4* pv = (const float4*)(g_P + (size_t)vv * 512 + 256);  // cols 256..511
    const float4* b4 = (const float4*)W_edge_b;
    float4* o4 = (float4*)(out + (size_t)w * OD);
#pragma unroll
    for (int i = 0; i < 2; i++) {
        int idx = lane + i * 32;  // 0..63
        float4 a = pu[idx];
        float4 c = pv[idx];
        float4 bb = __ldg(&b4[idx]);
        float4 r = make_float4(a.x + c.x + bb.x, a.y + c.y + bb.y,
                               a.z + c.z + bb.z, a.w + c.w + bb.w);
        __stcs(&o4[idx], r);   // streaming store — evict-first, don't pollute L2
    }
}

// ---------------- launcher ----------------
extern "C" void kernel_launch(void* const* d_in, const int* in_sizes, int n_in,
                              void* d_out, int out_size) {
    const float* nfeats    = (const float*)d_in[0];  // [N,1,128]
    const float* efeats    = (const float*)d_in[1];  // [E,1,128]
    const int*   u         = (const int*)d_in[2];    // [E]
    const int*   v         = (const int*)d_in[3];    // [E]
    const float* W_apply_w = (const float*)d_in[4];  // [128,256]
    const float* W_apply_b = (const float*)d_in[5];  // [128]
    const float* W_edge_w  = (const float*)d_in[6];  // [256,256]
    const float* W_edge_b  = (const float*)d_in[7];  // [256]
    (void)n_in; (void)out_size;

    const int N = in_sizes[0] / FD;   // 50000
    const int E = in_sizes[2];        // 800000

    float* h_out    = (float*)d_out;                       // [N,128]
    float* edge_out = (float*)d_out + (size_t)N * HD;      // [E,256]

    // 1. zero scratch
    zero_kernel<<<512, 512>>>(N);

    // 2. segment sums + counts (vector RED atomics)
    {
        int warps_per_block = 8;
        int blocks = (E + warps_per_block - 1) / warps_per_block;
        scatter_kernel<<<blocks, warps_per_block * 32>>>(efeats, v, E);
    }

    // 3. build cat = [nfeats | mean]
    {
        int total4 = N * 64;
        cat_kernel<<<(total4 + 255) / 256, 256>>>(nfeats, N);
    }

    // 3b. pack Wcat (independent of 1-3; cheap)
    wpack_kernel<<<(512 * 32 + 255) / 256, 256>>>(W_edge_w);

    // 4+5. fused: h = relu(cat@Wa^T+b); P = h@Wcat^T
    {
        const int smem_bytes = (128 * 132 + 2 * 16 * 132) * (int)sizeof(float); // 84480
        cudaFuncSetAttribute(gemm45_kernel,
                             cudaFuncAttributeMaxDynamicSharedMemorySize, smem_bytes);
        int grid = (N + 127) / 128;
        gemm45_kernel<<<grid, 256, smem_bytes>>>(W_apply_w, W_apply_b, h_out, N);
    }

    // 6. edge = P_u[u] + P_v[v] + b
    {
        int warps_per_block = 8;
        int blocks = (E + warps_per_block - 1) / warps_per_block;
        edge_kernel<<<blocks, warps_per_block * 32>>>(u, v, W_edge_b, edge_out, E);
    }
}

// round 9
// speedup vs baseline: 1.3164x; 1.0292x over previous
#include <cuda_runtime.h>
#include <cuda_bf16.h>
#include <cstdint>

// Problem constants (fixed by the dataset)
#define MAXN 50000
#define MAXE 800000
#define FD   128     // node/edge feature dim
#define HD   128     // h dim
#define OD   256     // edge output dim

// ---------------- device scratch (no allocations allowed) ----------------
__device__ float g_sum[(size_t)MAXN * FD];      // segment sums of efeats by v
__device__ int   g_cnt[MAXN];                   // in-degree
__device__ float g_P[(size_t)MAXN * 512];       // [P_u (256) | P_v (256)] per node
__device__ float g_Wcat[512 * 128];             // packed [W_u ; W_v], rows=512 outs, k=128

// ---------------- kernel 1: zero scratch ----------------
__global__ void zero_kernel(int N) {
    size_t total4 = (size_t)N * (FD / 4);
    float4 z = make_float4(0.f, 0.f, 0.f, 0.f);
    float4* s4 = (float4*)g_sum;
    for (size_t i = (size_t)blockIdx.x * blockDim.x + threadIdx.x; i < total4;
         i += (size_t)gridDim.x * blockDim.x)
        s4[i] = z;
    for (int i = blockIdx.x * blockDim.x + threadIdx.x; i < N;
         i += gridDim.x * blockDim.x)
        g_cnt[i] = 0;
}

// ---------------- kernel 2: scatter mean via vector RED ----------------
// one warp per edge; each lane issues ONE red.global.add.v4.f32
__global__ void scatter_kernel(const float* __restrict__ efeats,
                               const int* __restrict__ v, int E) {
    int w = (blockIdx.x * blockDim.x + threadIdx.x) >> 5;
    int lane = threadIdx.x & 31;
    if (w >= E) return;
    int dst = __ldg(&v[w]);
    float4 val = __ldg(((const float4*)(efeats + (size_t)w * FD)) + lane);
    float* s = g_sum + (size_t)dst * FD + lane * 4;
    asm volatile("red.global.add.v4.f32 [%0], {%1, %2, %3, %4};"
                 :: "l"(s), "f"(val.x), "f"(val.y), "f"(val.z), "f"(val.w)
                 : "memory");
    if (lane == 0) atomicAdd(&g_cnt[dst], 1);
}

// ---------------- kernel 3b: pack Wcat = [W_u ; W_v] ----------------
__global__ void wpack_kernel(const float* __restrict__ W_edge_w) {
    int t = blockIdx.x * blockDim.x + threadIdx.x;  // 512*32 float4 = 16384
    if (t >= 512 * 32) return;
    int n = t >> 5;
    int kq = t & 31;
    const float* src = (n < 256) ? (W_edge_w + (size_t)n * 256 + kq * 4)
                                 : (W_edge_w + (size_t)(n - 256) * 256 + 128 + kq * 4);
    ((float4*)g_Wcat)[t] = *(const float4*)src;
}

// ---------------- fused GEMM: h = relu([nfeats|mean]@Wa^T + b); P = h@Wcat^T
// One 128-row M-tile per block, 256 threads, 8x8 microtile.
// Double-buffered smem tiles, register-staged global loads, 1 sync/iter.
// "cat" is virtual: A-loads read nfeats (k<128) or g_sum*inv(cnt) (k>=128).
__global__ __launch_bounds__(256, 2) void gemm45_kernel(
    const float* __restrict__ nfeats,  // [M][128]
    const float* __restrict__ Wa,      // [128][256]
    const float* __restrict__ Wab,     // [128]
    float* __restrict__ h_out,         // [M][128]
    int M)
{
    extern __shared__ float smem[];
    float* h_s = smem;                      // [128][132]  indexed [k][m]
    float* As  = smem + 128 * 132;          // 2 x [16][132]
    float* Bs  = As + 2 * 16 * 132;         // 2 x [16][132]

    const int tid = threadIdx.x;
    const int bm = blockIdx.x * 128;
    const int tx = tid & 15;
    const int ty = tid >> 4;
    const int tm = ty * 8;
    const int tn = tx * 8;

    // per-thread load slots (2 slots covering the 128x16 tile as 512 float4)
    const int row0 = tid >> 2;               // slot tid
    const int kq0  = tid & 3;
    const int row1 = (tid + 256) >> 2;       // slot tid+256
    const int kq1  = (tid + 256) & 3;

    float acc[8][8];
#pragma unroll
    for (int i = 0; i < 8; i++)
#pragma unroll
        for (int j = 0; j < 8; j++) acc[i][j] = 0.0f;

    float4 a_reg[2], b_reg[2];

    // ---- stage-1 tile load (virtual cat) into registers ----
    auto load1 = [&](int k0) {
#pragma unroll
        for (int i = 0; i < 2; i++) {
            int row = i ? row1 : row0;
            int kq  = i ? kq1  : kq0;
            int gm = bm + row;
            int k = k0 + kq * 4;
            float4 a = make_float4(0.f, 0.f, 0.f, 0.f);
            if (gm < M) {
                if (k < 128) {
                    a = *(const float4*)(nfeats + (size_t)gm * 128 + k);
                } else {
                    a = *(const float4*)(g_sum + (size_t)gm * 128 + (k - 128));
                    float inv = 1.0f / fmaxf((float)__ldg(&g_cnt[gm]), 1.0f);
                    a.x *= inv; a.y *= inv; a.z *= inv; a.w *= inv;
                }
            }
            a_reg[i] = a;
            b_reg[i] = *(const float4*)(Wa + (size_t)row * 256 + k);
        }
    };
    auto store1 = [&](int buf) {
        float* Ab = As + buf * 16 * 132;
        float* Bb = Bs + buf * 16 * 132;
#pragma unroll
        for (int i = 0; i < 2; i++) {
            int row = i ? row1 : row0;
            int kq  = i ? kq1  : kq0;
            Ab[(kq * 4 + 0) * 132 + row] = a_reg[i].x;
            Ab[(kq * 4 + 1) * 132 + row] = a_reg[i].y;
            Ab[(kq * 4 + 2) * 132 + row] = a_reg[i].z;
            Ab[(kq * 4 + 3) * 132 + row] = a_reg[i].w;
            Bb[(kq * 4 + 0) * 132 + row] = b_reg[i].x;
            Bb[(kq * 4 + 1) * 132 + row] = b_reg[i].y;
            Bb[(kq * 4 + 2) * 132 + row] = b_reg[i].z;
            Bb[(kq * 4 + 3) * 132 + row] = b_reg[i].w;
        }
    };
    auto fma1 = [&](int buf) {
        const float* Ab = As + buf * 16 * 132;
        const float* Bb = Bs + buf * 16 * 132;
#pragma unroll
        for (int kk = 0; kk < 16; kk++) {
            float4 a0 = *(const float4*)&Ab[kk * 132 + tm];
            float4 a1 = *(const float4*)&Ab[kk * 132 + tm + 4];
            float4 b0 = *(const float4*)&Bb[kk * 132 + tn];
            float4 b1 = *(const float4*)&Bb[kk * 132 + tn + 4];
            float a[8] = {a0.x, a0.y, a0.z, a0.w, a1.x, a1.y, a1.z, a1.w};
            float b[8] = {b0.x, b0.y, b0.z, b0.w, b1.x, b1.y, b1.z, b1.w};
#pragma unroll
            for (int i = 0; i < 8; i++)
#pragma unroll
                for (int j = 0; j < 8; j++) acc[i][j] += a[i] * b[j];
        }
    };

    // ---------------- stage 1: K=256, 16 pipelined iterations ------------
    load1(0);
    store1(0);
    __syncthreads();
#pragma unroll 1
    for (int it = 0; it < 16; it++) {
        int cur = it & 1;
        if (it < 15) load1((it + 1) * 16);   // LDG issue, overlaps FMA
        fma1(cur);
        if (it < 15) {
            store1(1 - cur);
            __syncthreads();
        }
    }

    // epilogue 1: bias + relu, write h (streaming) + h_s (transposed)
#pragma unroll
    for (int j = 0; j < 8; j++) {
        float bj = __ldg(&Wab[tn + j]);
#pragma unroll
        for (int i = 0; i < 8; i++)
            acc[i][j] = fmaxf(acc[i][j] + bj, 0.0f);
    }
#pragma unroll
    for (int i = 0; i < 8; i++) {
        int gm = bm + tm + i;
        if (gm < M) {
            float* cp = h_out + (size_t)gm * HD + tn;
            __stcs((float4*)(cp + 0),
                   make_float4(acc[i][0], acc[i][1], acc[i][2], acc[i][3]));
            __stcs((float4*)(cp + 4),
                   make_float4(acc[i][4], acc[i][5], acc[i][6], acc[i][7]));
        }
    }
#pragma unroll
    for (int j = 0; j < 8; j++) {
        *(float4*)&h_s[(tn + j) * 132 + tm] =
            make_float4(acc[0][j], acc[1][j], acc[2][j], acc[3][j]);
        *(float4*)&h_s[(tn + j) * 132 + tm + 4] =
            make_float4(acc[4][j], acc[5][j], acc[6][j], acc[7][j]);
    }

    // ---------------- stage 2: P = h @ Wcat^T, 4 chunks, K=128 ----------
    auto load2 = [&](int chunk, int k0) {
#pragma unroll
        for (int i = 0; i < 2; i++) {
            int row = i ? row1 : row0;
            int kq  = i ? kq1  : kq0;
            b_reg[i] = *(const float4*)(g_Wcat +
                        (size_t)(chunk * 128 + row) * 128 + k0 + kq * 4);
        }
    };
    auto store2 = [&](int buf) {
        float* Bb = Bs + buf * 16 * 132;
#pragma unroll
        for (int i = 0; i < 2; i++) {
            int row = i ? row1 : row0;
            int kq  = i ? kq1  : kq0;
            Bb[(kq * 4 + 0) * 132 + row] = b_reg[i].x;
            Bb[(kq * 4 + 1) * 132 + row] = b_reg[i].y;
            Bb[(kq * 4 + 2) * 132 + row] = b_reg[i].z;
            Bb[(kq * 4 + 3) * 132 + row] = b_reg[i].w;
        }
    };

#pragma unroll 1
    for (int chunk = 0; chunk < 4; chunk++) {
#pragma unroll
        for (int i = 0; i < 8; i++)
#pragma unroll
            for (int j = 0; j < 8; j++) acc[i][j] = 0.0f;

        load2(chunk, 0);
        store2(0);
        __syncthreads();   // also orders h_s writes before first chunk's reads

#pragma unroll 1
        for (int it = 0; it < 8; it++) {
            int cur = it & 1;
            if (it < 7) load2(chunk, (it + 1) * 16);
            {
                const float* Bb = Bs + cur * 16 * 132;
                const float* Ab = h_s + it * 16 * 132;   // A k-rows it*16..it*16+15
#pragma unroll
                for (int kk = 0; kk < 16; kk++) {
                    float4 a0 = *(const float4*)&Ab[kk * 132 + tm];
                    float4 a1 = *(const float4*)&Ab[kk * 132 + tm + 4];
                    float4 b0 = *(const float4*)&Bb[kk * 132 + tn];
                    float4 b1 = *(const float4*)&Bb[kk * 132 + tn + 4];
                    float a[8] = {a0.x, a0.y, a0.z, a0.w, a1.x, a1.y, a1.z, a1.w};
                    float b[8] = {b0.x, b0.y, b0.z, b0.w, b1.x, b1.y, b1.z, b1.w};
#pragma unroll
                    for (int i = 0; i < 8; i++)
#pragma unroll
                        for (int j = 0; j < 8; j++) acc[i][j] += a[i] * b[j];
                }
            }
            if (it < 7) {
                store2(1 - cur);
                __syncthreads();
            }
        }

#pragma unroll
        for (int i = 0; i < 8; i++) {
            int gm = bm + tm + i;
            if (gm < M) {
                float* cp = g_P + (size_t)gm * 512 + chunk * 128 + tn;
                *(float4*)(cp + 0) = make_float4(acc[i][0], acc[i][1], acc[i][2], acc[i][3]);
                *(float4*)(cp + 4) = make_float4(acc[i][4], acc[i][5], acc[i][6], acc[i][7]);
            }
        }
    }
}

// ---------------- kernel 6: edge output = P_u[u] + P_v[v] + b -----------
// one warp per edge; streaming stores keep g_P resident in L2
__global__ void edge_kernel(const int* __restrict__ u,
                            const int* __restrict__ v,
                            const float* __restrict__ W_edge_b,
                            float* __restrict__ out, int E) {
    int w = (blockIdx.x * blockDim.x + threadIdx.x) >> 5;
    int lane = threadIdx.x & 31;
    if (w >= E) return;
    int uu = __ldg(&u[w]);
    int vv = __ldg(&v[w]);
    const float4* pu = (const float4*)(g_P + (size_t)uu * 512);        // cols 0..255
    const float4* pv = (const float4*)(g_P + (size_t)vv * 512 + 256);  // cols 256..511
    const float4* b4 = (const float4*)W_edge_b;
    float4* o4 = (float4*)(out + (size_t)w * OD);
#pragma unroll
    for (int i = 0; i < 2; i++) {
        int idx = lane + i * 32;  // 0..63
        float4 a = pu[idx];
        float4 c = pv[idx];
        float4 bb = __ldg(&b4[idx]);
        float4 r = make_float4(a.x + c.x + bb.x, a.y + c.y + bb.y,
                               a.z + c.z + bb.z, a.w + c.w + bb.w);
        __stcs(&o4[idx], r);   // streaming store — evict-first, don't pollute L2
    }
}

// ---------------- launcher ----------------
extern "C" void kernel_launch(void* const* d_in, const int* in_sizes, int n_in,
                              void* d_out, int out_size) {
    const float* nfeats    = (const float*)d_in[0];  // [N,1,128]
    const float* efeats    = (const float*)d_in[1];  // [E,1,128]
    const int*   u         = (const int*)d_in[2];    // [E]
    const int*   v         = (const int*)d_in[3];    // [E]
    const float* W_apply_w = (const float*)d_in[4];  // [128,256]
    const float* W_apply_b = (const float*)d_in[5];  // [128]
    const float* W_edge_w  = (const float*)d_in[6];  // [256,256]
    const float* W_edge_b  = (const float*)d_in[7];  // [256]
    (void)n_in; (void)out_size;

    const int N = in_sizes[0] / FD;   // 50000
    const int E = in_sizes[2];        // 800000

    float* h_out    = (float*)d_out;                       // [N,128]
    float* edge_out = (float*)d_out + (size_t)N * HD;      // [E,256]

    // 1. zero scratch
    zero_kernel<<<512, 512>>>(N);

    // 2. segment sums + counts (vector RED atomics)
    {
        int warps_per_block = 8;
        int blocks = (E + warps_per_block - 1) / warps_per_block;
        scatter_kernel<<<blocks, warps_per_block * 32>>>(efeats, v, E);
    }

    // 3b. pack Wcat (cheap, independent)
    wpack_kernel<<<(512 * 32 + 255) / 256, 256>>>(W_edge_w);

    // 4+5. fused pipelined GEMM: h = relu(cat@Wa^T+b); P = h@Wcat^T
    {
        const int smem_bytes = (128 * 132 + 4 * 16 * 132) * (int)sizeof(float); // 101376
        cudaFuncSetAttribute(gemm45_kernel,
                             cudaFuncAttributeMaxDynamicSharedMemorySize, smem_bytes);
        int grid = (N + 127) / 128;
        gemm45_kernel<<<grid, 256, smem_bytes>>>(nfeats, W_apply_w, W_apply_b,
                                                 h_out, N);
    }

    // 6. edge = P_u[u] + P_v[v] + b
    {
        int warps_per_block = 8;
        int blocks = (E + warps_per_block - 1) / warps_per_block;
        edge_kernel<<<blocks, warps_per_block * 32>>>(u, v, W_edge_b, edge_out, E);
    }
}

// round 12
// speedup vs baseline: 1.3463x; 1.0227x over previous
#include <cuda_runtime.h>
#include <cuda_bf16.h>
#include <cstdint>

// Problem constants (fixed by the dataset)
#define MAXN 50000
#define MAXE 800000
#define FD   128     // node/edge feature dim
#define HD   128     // h dim
#define OD   256     // edge output dim

// ---------------- device scratch (no allocations allowed) ----------------
__device__ float g_sum[(size_t)MAXN * FD];      // segment sums of efeats by v
__device__ int   g_cnt[MAXN];                   // in-degree
__device__ float g_P[(size_t)MAXN * 512];       // [P_u (256) | P_v (256)] per node
__device__ float g_Wcat[512 * 128];             // packed [W_u ; W_v], rows=512 outs, k=128

// ---------------- packed f32x2 helpers (sm_100+; ptxas never emits these) --
__device__ __forceinline__ void fma2(unsigned long long& d,
                                     unsigned long long a,
                                     unsigned long long b) {
    asm("fma.rn.f32x2 %0, %1, %2, %0;" : "+l"(d) : "l"(a), "l"(b));
}
__device__ __forceinline__ unsigned long long splat2(float x) {
    unsigned long long r;
    asm("mov.b64 %0, {%1, %1};" : "=l"(r) : "f"(x));
    return r;
}
__device__ __forceinline__ void unpack2(float& lo, float& hi, unsigned long long p) {
    asm("mov.b64 {%0, %1}, %2;" : "=f"(lo), "=f"(hi) : "l"(p));
}

// ---------------- kernel 1: zero scratch ----------------
__global__ void zero_kernel(int N) {
    size_t total4 = (size_t)N * (FD / 4);
    float4 z = make_float4(0.f, 0.f, 0.f, 0.f);
    float4* s4 = (float4*)g_sum;
    for (size_t i = (size_t)blockIdx.x * blockDim.x + threadIdx.x; i < total4;
         i += (size_t)gridDim.x * blockDim.x)
        s4[i] = z;
    for (int i = blockIdx.x * blockDim.x + threadIdx.x; i < N;
         i += gridDim.x * blockDim.x)
        g_cnt[i] = 0;
}

// ---------------- kernel 2: scatter mean via vector RED ----------------
// one warp per edge; each lane issues ONE red.global.add.v4.f32
__global__ void scatter_kernel(const float* __restrict__ efeats,
                               const int* __restrict__ v, int E) {
    int w = (blockIdx.x * blockDim.x + threadIdx.x) >> 5;
    int lane = threadIdx.x & 31;
    if (w >= E) return;
    int dst = __ldg(&v[w]);
    float4 val = __ldg(((const float4*)(efeats + (size_t)w * FD)) + lane);
    float* s = g_sum + (size_t)dst * FD + lane * 4;
    asm volatile("red.global.add.v4.f32 [%0], {%1, %2, %3, %4};"
                 :: "l"(s), "f"(val.x), "f"(val.y), "f"(val.z), "f"(val.w)
                 : "memory");
    if (lane == 0) atomicAdd(&g_cnt[dst], 1);
}

// ---------------- kernel 3b: pack Wcat = [W_u ; W_v] ----------------
__global__ void wpack_kernel(const float* __restrict__ W_edge_w) {
    int t = blockIdx.x * blockDim.x + threadIdx.x;  // 512*32 float4 = 16384
    if (t >= 512 * 32) return;
    int n = t >> 5;
    int kq = t & 31;
    const float* src = (n < 256) ? (W_edge_w + (size_t)n * 256 + kq * 4)
                                 : (W_edge_w + (size_t)(n - 256) * 256 + 128 + kq * 4);
    ((float4*)g_Wcat)[t] = *(const float4*)src;
}

// ---------------- fused GEMM: h = relu([nfeats|mean]@Wa^T + b); P = h@Wcat^T
// One 128-row M-tile per block, 256 threads, 8x8 microtile.
// Double-buffered smem, register-staged global loads, 1 sync/iter.
// Inner loops use packed fma.rn.f32x2 (2 FLOP-pairs per fma-pipe slot).
__global__ __launch_bounds__(256, 2) void gemm45_kernel(
    const float* __restrict__ nfeats,  // [M][128]
    const float* __restrict__ Wa,      // [128][256]
    const float* __restrict__ Wab,     // [128]
    float* __restrict__ h_out,         // [M][128]
    int M)
{
    extern __shared__ float smem[];
    float* h_s = smem;                      // [128][132]  indexed [k][m]
    float* As  = smem + 128 * 132;          // 2 x [16][132]
    float* Bs  = As + 2 * 16 * 132;         // 2 x [16][132]

    const int tid = threadIdx.x;
    const int bm = blockIdx.x * 128;
    const int tx = tid & 15;
    const int ty = tid >> 4;
    const int tm = ty * 8;
    const int tn = tx * 8;

    // per-thread load slots (2 slots covering the 128x16 tile as 512 float4)
    const int row0 = tid >> 2;
    const int kq0  = tid & 3;
    const int row1 = (tid + 256) >> 2;
    const int kq1  = (tid + 256) & 3;

    // packed accumulators: acc2[i][jp] holds columns (tn+2*jp, tn+2*jp+1), row tm+i
    unsigned long long acc2[8][4];
#pragma unroll
    for (int i = 0; i < 8; i++)
#pragma unroll
        for (int jp = 0; jp < 4; jp++) acc2[i][jp] = 0ull;

    float4 a_reg[2], b_reg[2];

    // ---- stage-1 tile load (virtual cat) into registers ----
    auto load1 = [&](int k0) {
#pragma unroll
        for (int i = 0; i < 2; i++) {
            int row = i ? row1 : row0;
            int kq  = i ? kq1  : kq0;
            int gm = bm + row;
            int k = k0 + kq * 4;
            float4 a = make_float4(0.f, 0.f, 0.f, 0.f);
            if (gm < M) {
                if (k < 128) {
                    a = *(const float4*)(nfeats + (size_t)gm * 128 + k);
                } else {
                    a = *(const float4*)(g_sum + (size_t)gm * 128 + (k - 128));
                    float inv = 1.0f / fmaxf((float)__ldg(&g_cnt[gm]), 1.0f);
                    a.x *= inv; a.y *= inv; a.z *= inv; a.w *= inv;
                }
            }
            a_reg[i] = a;
            b_reg[i] = *(const float4*)(Wa + (size_t)row * 256 + k);
        }
    };
    auto store1 = [&](int buf) {
        float* Ab = As + buf * 16 * 132;
        float* Bb = Bs + buf * 16 * 132;
#pragma unroll
        for (int i = 0; i < 2; i++) {
            int row = i ? row1 : row0;
            int kq  = i ? kq1  : kq0;
            Ab[(kq * 4 + 0) * 132 + row] = a_reg[i].x;
            Ab[(kq * 4 + 1) * 132 + row] = a_reg[i].y;
            Ab[(kq * 4 + 2) * 132 + row] = a_reg[i].z;
            Ab[(kq * 4 + 3) * 132 + row] = a_reg[i].w;
            Bb[(kq * 4 + 0) * 132 + row] = b_reg[i].x;
            Bb[(kq * 4 + 1) * 132 + row] = b_reg[i].y;
            Bb[(kq * 4 + 2) * 132 + row] = b_reg[i].z;
            Bb[(kq * 4 + 3) * 132 + row] = b_reg[i].w;
        }
    };
    // packed-FMA inner block: A rows from Ab, B (packed pairs) from Bb
    auto fma_block = [&](const float* Ab, const float* Bb) {
#pragma unroll
        for (int kk = 0; kk < 16; kk++) {
            float4 a0 = *(const float4*)&Ab[kk * 132 + tm];
            float4 a1 = *(const float4*)&Ab[kk * 132 + tm + 4];
            ulonglong2 p0 = *(const ulonglong2*)&Bb[kk * 132 + tn];      // cols tn..tn+3
            ulonglong2 p1 = *(const ulonglong2*)&Bb[kk * 132 + tn + 4];  // cols tn+4..tn+7
            unsigned long long b2[4] = {p0.x, p0.y, p1.x, p1.y};
            float af[8] = {a0.x, a0.y, a0.z, a0.w, a1.x, a1.y, a1.z, a1.w};
#pragma unroll
            for (int i = 0; i < 8; i++) {
                unsigned long long aa = splat2(af[i]);
#pragma unroll
                for (int jp = 0; jp < 4; jp++) fma2(acc2[i][jp], aa, b2[jp]);
            }
        }
    };

    // ---------------- stage 1: K=256, 16 pipelined iterations ------------
    load1(0);
    store1(0);
    __syncthreads();
#pragma unroll 1
    for (int it = 0; it < 16; it++) {
        int cur = it & 1;
        if (it < 15) load1((it + 1) * 16);   // LDG issue, overlaps FMA
        fma_block(As + cur * 16 * 132, Bs + cur * 16 * 132);
        if (it < 15) {
            store1(1 - cur);
            __syncthreads();
        }
    }

    // epilogue 1: unpack, bias + relu, write h (streaming) + h_s (transposed)
    float hv[8][8];
#pragma unroll
    for (int i = 0; i < 8; i++)
#pragma unroll
        for (int jp = 0; jp < 4; jp++)
            unpack2(hv[i][2 * jp], hv[i][2 * jp + 1], acc2[i][jp]);
#pragma unroll
    for (int j = 0; j < 8; j++) {
        float bj = __ldg(&Wab[tn + j]);
#pragma unroll
        for (int i = 0; i < 8; i++)
            hv[i][j] = fmaxf(hv[i][j] + bj, 0.0f);
    }
#pragma unroll
    for (int i = 0; i < 8; i++) {
        int gm = bm + tm + i;
        if (gm < M) {
            float* cp = h_out + (size_t)gm * HD + tn;
            __stcs((float4*)(cp + 0),
                   make_float4(hv[i][0], hv[i][1], hv[i][2], hv[i][3]));
            __stcs((float4*)(cp + 4),
                   make_float4(hv[i][4], hv[i][5], hv[i][6], hv[i][7]));
        }
    }
#pragma unroll
    for (int j = 0; j < 8; j++) {
        *(float4*)&h_s[(tn + j) * 132 + tm] =
            make_float4(hv[0][j], hv[1][j], hv[2][j], hv[3][j]);
        *(float4*)&h_s[(tn + j) * 132 + tm + 4] =
            make_float4(hv[4][j], hv[5][j], hv[6][j], hv[7][j]);
    }

    // ---------------- stage 2: P = h @ Wcat^T, 4 chunks, K=128 ----------
    auto load2 = [&](int chunk, int k0) {
#pragma unroll
        for (int i = 0; i < 2; i++) {
            int row = i ? row1 : row0;
            int kq  = i ? kq1  : kq0;
            b_reg[i] = *(const float4*)(g_Wcat +
                        (size_t)(chunk * 128 + row) * 128 + k0 + kq * 4);
        }
    };
    auto store2 = [&](int buf) {
        float* Bb = Bs + buf * 16 * 132;
#pragma unroll
        for (int i = 0; i < 2; i++) {
            int row = i ? row1 : row0;
            int kq  = i ? kq1  : kq0;
            Bb[(kq * 4 + 0) * 132 + row] = b_reg[i].x;
            Bb[(kq * 4 + 1) * 132 + row] = b_reg[i].y;
            Bb[(kq * 4 + 2) * 132 + row] = b_reg[i].z;
            Bb[(kq * 4 + 3) * 132 + row] = b_reg[i].w;
        }
    };

#pragma unroll 1
    for (int chunk = 0; chunk < 4; chunk++) {
#pragma unroll
        for (int i = 0; i < 8; i++)
#pragma unroll
            for (int jp = 0; jp < 4; jp++) acc2[i][jp] = 0ull;

        load2(chunk, 0);
        store2(0);
        __syncthreads();   // also orders h_s writes before first chunk's reads

#pragma unroll 1
        for (int it = 0; it < 8; it++) {
            int cur = it & 1;
            if (it < 7) load2(chunk, (it + 1) * 16);
            fma_block(h_s + it * 16 * 132, Bs + cur * 16 * 132);
            if (it < 7) {
                store2(1 - cur);
                __syncthreads();
            }
        }

#pragma unroll
        for (int i = 0; i < 8; i++) {
            int gm = bm + tm + i;
            if (gm < M) {
                float r[8];
#pragma unroll
                for (int jp = 0; jp < 4; jp++)
                    unpack2(r[2 * jp], r[2 * jp + 1], acc2[i][jp]);
                float* cp = g_P + (size_t)gm * 512 + chunk * 128 + tn;
                *(float4*)(cp + 0) = make_float4(r[0], r[1], r[2], r[3]);
                *(float4*)(cp + 4) = make_float4(r[4], r[5], r[6], r[7]);
            }
        }
    }
}

// ---------------- kernel 6: edge output = P_u[u] + P_v[v] + b -----------
// one warp per edge; streaming stores keep g_P resident in L2
__global__ void edge_kernel(const int* __restrict__ u,
                            const int* __restrict__ v,
                            const float* __restrict__ W_edge_b,
                            float* __restrict__ out, int E) {
    int w = (blockIdx.x * blockDim.x + threadIdx.x) >> 5;
    int lane = threadIdx.x & 31;
    if (w >= E) return;
    int uu = __ldg(&u[w]);
    int vv = __ldg(&v[w]);
    const float4* pu = (const float4*)(g_P + (size_t)uu * 512);        // cols 0..255
    const float4* pv = (const float4*)(g_P + (size_t)vv * 512 + 256);  // cols 256..511
    const float4* b4 = (const float4*)W_edge_b;
    float4* o4 = (float4*)(out + (size_t)w * OD);
#pragma unroll
    for (int i = 0; i < 2; i++) {
        int idx = lane + i * 32;  // 0..63
        float4 a = pu[idx];
        float4 c = pv[idx];
        float4 bb = __ldg(&b4[idx]);
        float4 r = make_float4(a.x + c.x + bb.x, a.y + c.y + bb.y,
                               a.z + c.z + bb.z, a.w + c.w + bb.w);
        __stcs(&o4[idx], r);   // streaming store — evict-first, don't pollute L2
    }
}

// ---------------- launcher ----------------
extern "C" void kernel_launch(void* const* d_in, const int* in_sizes, int n_in,
                              void* d_out, int out_size) {
    const float* nfeats    = (const float*)d_in[0];  // [N,1,128]
    const float* efeats    = (const float*)d_in[1];  // [E,1,128]
    const int*   u         = (const int*)d_in[2];    // [E]
    const int*   v         = (const int*)d_in[3];    // [E]
    const float* W_apply_w = (const float*)d_in[4];  // [128,256]
    const float* W_apply_b = (const float*)d_in[5];  // [128]
    const float* W_edge_w  = (const float*)d_in[6];  // [256,256]
    const float* W_edge_b  = (const float*)d_in[7];  // [256]
    (void)n_in; (void)out_size;

    const int N = in_sizes[0] / FD;   // 50000
    const int E = in_sizes[2];        // 800000

    float* h_out    = (float*)d_out;                       // [N,128]
    float* edge_out = (float*)d_out + (size_t)N * HD;      // [E,256]

    // 1. zero scratch
    zero_kernel<<<512, 512>>>(N);

    // 2. segment sums + counts (vector RED atomics)
    {
        int warps_per_block = 8;
        int blocks = (E + warps_per_block - 1) / warps_per_block;
        scatter_kernel<<<blocks, warps_per_block * 32>>>(efeats, v, E);
    }

    // 3b. pack Wcat (cheap, independent)
    wpack_kernel<<<(512 * 32 + 255) / 256, 256>>>(W_edge_w);

    // 4+5. fused pipelined GEMM (packed f32x2): h = relu(cat@Wa^T+b); P = h@Wcat^T
    {
        const int smem_bytes = (128 * 132 + 4 * 16 * 132) * (int)sizeof(float); // 101376
        cudaFuncSetAttribute(gemm45_kernel,
                             cudaFuncAttributeMaxDynamicSharedMemorySize, smem_bytes);
        int grid = (N + 127) / 128;
        gemm45_kernel<<<grid, 256, smem_bytes>>>(nfeats, W_apply_w, W_apply_b,
                                                 h_out, N);
    }

    // 6. edge = P_u[u] + P_v[v] + b
    {
        int warps_per_block = 8;
        int blocks = (E + warps_per_block - 1) / warps_per_block;
        edge_kernel<<<blocks, warps_per_block * 32>>>(u, v, W_edge_b, edge_out, E);
    }
}

// round 13
// speedup vs baseline: 1.4431x; 1.0719x over previous
#include <cuda_runtime.h>
#include <cuda_bf16.h>
#include <cstdint>

// Problem constants (fixed by the dataset)
#define MAXN 50000
#define MAXE 800000
#define FD   128     // node/edge feature dim
#define HD   128     // h dim
#define OD   256     // edge output dim

// ---------------- device scratch (no allocations allowed) ----------------
__device__ float g_sum[(size_t)MAXN * FD];      // segment sums of efeats by v
__device__ int   g_cnt[MAXN];                   // in-degree
__device__ float g_P[(size_t)MAXN * 512];       // [P_u (256) | P_v (256)] per node
__device__ float g_Wcat[512 * 128];             // packed [W_u ; W_v], rows=512 outs, k=128

// ---------------- packed f32x2 helpers (sm_100+; ptxas never emits these) --
__device__ __forceinline__ void fma2(unsigned long long& d,
                                     unsigned long long a,
                                     unsigned long long b) {
    asm("fma.rn.f32x2 %0, %1, %2, %0;" : "+l"(d) : "l"(a), "l"(b));
}
__device__ __forceinline__ unsigned long long splat2(float x) {
    unsigned long long r;
    asm("mov.b64 %0, {%1, %1};" : "=l"(r) : "f"(x));
    return r;
}
__device__ __forceinline__ void unpack2(float& lo, float& hi, unsigned long long p) {
    asm("mov.b64 {%0, %1}, %2;" : "=f"(lo), "=f"(hi) : "l"(p));
}

// ---------------- kernel 1: zero scratch ----------------
__global__ void zero_kernel(int N) {
    size_t total4 = (size_t)N * (FD / 4);
    float4 z = make_float4(0.f, 0.f, 0.f, 0.f);
    float4* s4 = (float4*)g_sum;
    for (size_t i = (size_t)blockIdx.x * blockDim.x + threadIdx.x; i < total4;
         i += (size_t)gridDim.x * blockDim.x)
        s4[i] = z;
    for (int i = blockIdx.x * blockDim.x + threadIdx.x; i < N;
         i += gridDim.x * blockDim.x)
        g_cnt[i] = 0;
}

// ---------------- kernel 2: scatter mean via vector RED ----------------
__global__ void scatter_kernel(const float* __restrict__ efeats,
                               const int* __restrict__ v, int E) {
    int w = (blockIdx.x * blockDim.x + threadIdx.x) >> 5;
    int lane = threadIdx.x & 31;
    if (w >= E) return;
    int dst = __ldg(&v[w]);
    float4 val = __ldg(((const float4*)(efeats + (size_t)w * FD)) + lane);
    float* s = g_sum + (size_t)dst * FD + lane * 4;
    asm volatile("red.global.add.v4.f32 [%0], {%1, %2, %3, %4};"
                 :: "l"(s), "f"(val.x), "f"(val.y), "f"(val.z), "f"(val.w)
                 : "memory");
    if (lane == 0) atomicAdd(&g_cnt[dst], 1);
}

// ---------------- kernel 3b: pack Wcat = [W_u ; W_v] ----------------
__global__ void wpack_kernel(const float* __restrict__ W_edge_w) {
    int t = blockIdx.x * blockDim.x + threadIdx.x;  // 512*32 float4 = 16384
    if (t >= 512 * 32) return;
    int n = t >> 5;
    int kq = t & 31;
    const float* src = (n < 256) ? (W_edge_w + (size_t)n * 256 + kq * 4)
                                 : (W_edge_w + (size_t)(n - 256) * 256 + 128 + kq * 4);
    ((float4*)g_Wcat)[t] = *(const float4*)src;
}

// ---------------- fused GEMM: h = relu([nfeats|mean]@Wa^T + b); P = h@Wcat^T
// One 128-row M-tile per block, 256 threads, 8x8 microtile.
// Packed fma.rn.f32x2 inner loop. B-column split (tx*4 | 64+tx*4) makes every
// B LDS.128 contiguous across the 16 tx lanes -> zero bank conflicts.
__global__ __launch_bounds__(256, 2) void gemm45_kernel(
    const float* __restrict__ nfeats,  // [M][128]
    const float* __restrict__ Wa,      // [128][256]
    const float* __restrict__ Wab,     // [128]
    float* __restrict__ h_out,         // [M][128]
    int M)
{
    extern __shared__ float smem[];
    float* h_s = smem;                      // [128][132]  indexed [k][m]
    float* As  = smem + 128 * 132;          // 2 x [16][132]
    float* Bs  = As + 2 * 16 * 132;         // 2 x [16][132]

    const int tid = threadIdx.x;
    const int bm = blockIdx.x * 128;
    const int tx = tid & 15;
    const int ty = tid >> 4;
    const int tm = ty * 8;
    const int tn_lo = tx * 4;        // columns tn_lo..tn_lo+3
    const int tn_hi = 64 + tx * 4;   // columns tn_hi..tn_hi+3

    // per-thread load slots (2 slots covering the 128x16 tile as 512 float4)
    const int row0 = tid >> 2;
    const int kq0  = tid & 3;
    const int row1 = (tid + 256) >> 2;
    const int kq1  = (tid + 256) & 3;

    // acc2[i][jp]: jp 0..1 -> cols (tn_lo+2jp, +1); jp 2..3 -> cols (tn_hi+2(jp-2), +1)
    unsigned long long acc2[8][4];
#pragma unroll
    for (int i = 0; i < 8; i++)
#pragma unroll
        for (int jp = 0; jp < 4; jp++) acc2[i][jp] = 0ull;

    float4 a_reg[2], b_reg[2];

    // ---- stage-1 tile load (virtual cat) into registers ----
    auto load1 = [&](int k0) {
#pragma unroll
        for (int i = 0; i < 2; i++) {
            int row = i ? row1 : row0;
            int kq  = i ? kq1  : kq0;
            int gm = bm + row;
            int k = k0 + kq * 4;
            float4 a = make_float4(0.f, 0.f, 0.f, 0.f);
            if (gm < M) {
                if (k < 128) {
                    a = *(const float4*)(nfeats + (size_t)gm * 128 + k);
                } else {
                    a = *(const float4*)(g_sum + (size_t)gm * 128 + (k - 128));
                    float inv = 1.0f / fmaxf((float)__ldg(&g_cnt[gm]), 1.0f);
                    a.x *= inv; a.y *= inv; a.z *= inv; a.w *= inv;
                }
            }
            a_reg[i] = a;
            b_reg[i] = *(const float4*)(Wa + (size_t)row * 256 + k);
        }
    };
    auto store1 = [&](int buf) {
        float* Ab = As + buf * 16 * 132;
        float* Bb = Bs + buf * 16 * 132;
#pragma unroll
        for (int i = 0; i < 2; i++) {
            int row = i ? row1 : row0;
            int kq  = i ? kq1  : kq0;
            Ab[(kq * 4 + 0) * 132 + row] = a_reg[i].x;
            Ab[(kq * 4 + 1) * 132 + row] = a_reg[i].y;
            Ab[(kq * 4 + 2) * 132 + row] = a_reg[i].z;
            Ab[(kq * 4 + 3) * 132 + row] = a_reg[i].w;
            Bb[(kq * 4 + 0) * 132 + row] = b_reg[i].x;
            Bb[(kq * 4 + 1) * 132 + row] = b_reg[i].y;
            Bb[(kq * 4 + 2) * 132 + row] = b_reg[i].z;
            Bb[(kq * 4 + 3) * 132 + row] = b_reg[i].w;
        }
    };
    // packed-FMA inner block. B reads: 16B at tn_lo (contiguous across tx) and
    // 16B at tn_hi (contiguous) -> conflict-free LDS.128.
    auto fma_block = [&](const float* Ab, const float* Bb) {
#pragma unroll
        for (int kk = 0; kk < 16; kk++) {
            float4 a0 = *(const float4*)&Ab[kk * 132 + tm];
            float4 a1 = *(const float4*)&Ab[kk * 132 + tm + 4];
            ulonglong2 p0 = *(const ulonglong2*)&Bb[kk * 132 + tn_lo];
            ulonglong2 p1 = *(const ulonglong2*)&Bb[kk * 132 + tn_hi];
            unsigned long long b2[4] = {p0.x, p0.y, p1.x, p1.y};
            float af[8] = {a0.x, a0.y, a0.z, a0.w, a1.x, a1.y, a1.z, a1.w};
#pragma unroll
            for (int i = 0; i < 8; i++) {
                unsigned long long aa = splat2(af[i]);
#pragma unroll
                for (int jp = 0; jp < 4; jp++) fma2(acc2[i][jp], aa, b2[jp]);
            }
        }
    };

    // ---------------- stage 1: K=256, 16 pipelined iterations ------------
    load1(0);
    store1(0);
    __syncthreads();
#pragma unroll 1
    for (int it = 0; it < 16; it++) {
        int cur = it & 1;
        if (it < 15) load1((it + 1) * 16);   // LDG issue, overlaps FMA
        fma_block(As + cur * 16 * 132, Bs + cur * 16 * 132);
        if (it < 15) {
            store1(1 - cur);
            __syncthreads();
        }
    }

    // epilogue 1: unpack, bias + relu, write h (streaming) + h_s (transposed)
    // hv[i][j]: j 0..3 -> global col tn_lo+j ; j 4..7 -> global col tn_hi+(j-4)
    float hv[8][8];
#pragma unroll
    for (int i = 0; i < 8; i++)
#pragma unroll
        for (int jp = 0; jp < 4; jp++)
            unpack2(hv[i][2 * jp], hv[i][2 * jp + 1], acc2[i][jp]);
#pragma unroll
    for (int j = 0; j < 8; j++) {
        int col = (j < 4) ? (tn_lo + j) : (tn_hi + j - 4);
        float bj = __ldg(&Wab[col]);
#pragma unroll
        for (int i = 0; i < 8; i++)
            hv[i][j] = fmaxf(hv[i][j] + bj, 0.0f);
    }
#pragma unroll
    for (int i = 0; i < 8; i++) {
        int gm = bm + tm + i;
        if (gm < M) {
            float* cp = h_out + (size_t)gm * HD;
            __stcs((float4*)(cp + tn_lo),
                   make_float4(hv[i][0], hv[i][1], hv[i][2], hv[i][3]));
            __stcs((float4*)(cp + tn_hi),
                   make_float4(hv[i][4], hv[i][5], hv[i][6], hv[i][7]));
        }
    }
#pragma unroll
    for (int j = 0; j < 8; j++) {
        int col = (j < 4) ? (tn_lo + j) : (tn_hi + j - 4);
        *(float4*)&h_s[col * 132 + tm] =
            make_float4(hv[0][j], hv[1][j], hv[2][j], hv[3][j]);
        *(float4*)&h_s[col * 132 + tm + 4] =
            make_float4(hv[4][j], hv[5][j], hv[6][j], hv[7][j]);
    }

    // ---------------- stage 2: P = h @ Wcat^T, 4 chunks, K=128 ----------
    auto load2 = [&](int chunk, int k0) {
#pragma unroll
        for (int i = 0; i < 2; i++) {
            int row = i ? row1 : row0;
            int kq  = i ? kq1  : kq0;
            b_reg[i] = *(const float4*)(g_Wcat +
                        (size_t)(chunk * 128 + row) * 128 + k0 + kq * 4);
        }
    };
    auto store2 = [&](int buf) {
        float* Bb = Bs + buf * 16 * 132;
#pragma unroll
        for (int i = 0; i < 2; i++) {
            int row = i ? row1 : row0;
            int kq  = i ? kq1  : kq0;
            Bb[(kq * 4 + 0) * 132 + row] = b_reg[i].x;
            Bb[(kq * 4 + 1) * 132 + row] = b_reg[i].y;
            Bb[(kq * 4 + 2) * 132 + row] = b_reg[i].z;
            Bb[(kq * 4 + 3) * 132 + row] = b_reg[i].w;
        }
    };

#pragma unroll 1
    for (int chunk = 0; chunk < 4; chunk++) {
#pragma unroll
        for (int i = 0; i < 8; i++)
#pragma unroll
            for (int jp = 0; jp < 4; jp++) acc2[i][jp] = 0ull;

        load2(chunk, 0);
        store2(0);
        __syncthreads();   // also orders h_s writes before first chunk's reads

#pragma unroll 1
        for (int it = 0; it < 8; it++) {
            int cur = it & 1;
            if (it < 7) load2(chunk, (it + 1) * 16);
            fma_block(h_s + it * 16 * 132, Bs + cur * 16 * 132);
            if (it < 7) {
                store2(1 - cur);
                __syncthreads();
            }
        }

#pragma unroll
        for (int i = 0; i < 8; i++) {
            int gm = bm + tm + i;
            if (gm < M) {
                float r[8];
#pragma unroll
                for (int jp = 0; jp < 4; jp++)
                    unpack2(r[2 * jp], r[2 * jp + 1], acc2[i][jp]);
                float* cp = g_P + (size_t)gm * 512 + chunk * 128;
                *(float4*)(cp + tn_lo) = make_float4(r[0], r[1], r[2], r[3]);
                *(float4*)(cp + tn_hi) = make_float4(r[4], r[5], r[6], r[7]);
            }
        }
    }
}

// ---------------- kernel 6: edge output = P_u[u] + P_v[v] + b -----------
__global__ void edge_kernel(const int* __restrict__ u,
                            const int* __restrict__ v,
                            const float* __restrict__ W_edge_b,
                            float* __restrict__ out, int E) {
    int w = (blockIdx.x * blockDim.x + threadIdx.x) >> 5;
    int lane = threadIdx.x & 31;
    if (w >= E) return;
    int uu = __ldg(&u[w]);
    int vv = __ldg(&v[w]);
    const float4* pu = (const float4*)(g_P + (size_t)uu * 512);        // cols 0..255
    const float4* pv = (const float4*)(g_P + (size_t)vv * 512 + 256);  // cols 256..511
    const float4* b4 = (const float4*)W_edge_b;
    float4* o4 = (float4*)(out + (size_t)w * OD);
#pragma unroll
    for (int i = 0; i < 2; i++) {
        int idx = lane + i * 32;  // 0..63
        float4 a = pu[idx];
        float4 c = pv[idx];
        float4 bb = __ldg(&b4[idx]);
        float4 r = make_float4(a.x + c.x + bb.x, a.y + c.y + bb.y,
                               a.z + c.z + bb.z, a.w + c.w + bb.w);
        __stcs(&o4[idx], r);   // streaming store — evict-first, don't pollute L2
    }
}

// ---------------- launcher ----------------
extern "C" void kernel_launch(void* const* d_in, const int* in_sizes, int n_in,
                              void* d_out, int out_size) {
    const float* nfeats    = (const float*)d_in[0];  // [N,1,128]
    const float* efeats    = (const float*)d_in[1];  // [E,1,128]
    const int*   u         = (const int*)d_in[2];    // [E]
    const int*   v         = (const int*)d_in[3];    // [E]
    const float* W_apply_w = (const float*)d_in[4];  // [128,256]
    const float* W_apply_b = (const float*)d_in[5];  // [128]
    const float* W_edge_w  = (const float*)d_in[6];  // [256,256]
    const float* W_edge_b  = (const float*)d_in[7];  // [256]
    (void)n_in; (void)out_size;

    const int N = in_sizes[0] / FD;   // 50000
    const int E = in_sizes[2];        // 800000

    float* h_out    = (float*)d_out;                       // [N,128]
    float* edge_out = (float*)d_out + (size_t)N * HD;      // [E,256]

    // 1. zero scratch
    zero_kernel<<<512, 512>>>(N);

    // 2. segment sums + counts (vector RED atomics)
    {
        int warps_per_block = 8;
        int blocks = (E + warps_per_block - 1) / warps_per_block;
        scatter_kernel<<<blocks, warps_per_block * 32>>>(efeats, v, E);
    }

    // 3b. pack Wcat (cheap, independent)
    wpack_kernel<<<(512 * 32 + 255) / 256, 256>>>(W_edge_w);

    // 4+5. fused pipelined GEMM (packed f32x2, conflict-free B LDS)
    {
        const int smem_bytes = (128 * 132 + 4 * 16 * 132) * (int)sizeof(float); // 101376
        cudaFuncSetAttribute(gemm45_kernel,
                             cudaFuncAttributeMaxDynamicSharedMemorySize, smem_bytes);
        int grid = (N + 127) / 128;
        gemm45_kernel<<<grid, 256, smem_bytes>>>(nfeats, W_apply_w, W_apply_b,
                                                 h_out, N);
    }

    // 6. edge = P_u[u] + P_v[v] + b
    {
        int warps_per_block = 8;
        int blocks = (E + warps_per_block - 1) / warps_per_block;
        edge_kernel<<<blocks, warps_per_block * 32>>>(u, v, W_edge_b, edge_out, E);
    }
}